// round 9
// baseline (speedup 1.0000x reference)
#include <cuda_runtime.h>

#define NQ 25
#define KVD 9
#define ROW 225
#define WPB 2              // warps per block
#define SPW 4              // samples per warp
#define SPB (WPB*SPW)      // 8
#define THREADS (WPB*32)   // 64
#define KVSTRIDE 12        // u64 per K|V row (96B)
#define QSTRIDE 5

typedef unsigned long long u64;

__device__ __forceinline__ u64 pk(float lo, float hi) {
    u64 r; asm("mov.b64 %0,{%1,%2};" : "=l"(r) : "f"(lo), "f"(hi)); return r;
}
__device__ __forceinline__ void unpk(u64 v, float& lo, float& hi) {
    asm("mov.b64 {%0,%1},%2;" : "=f"(lo), "=f"(hi) : "l"(v));
}
__device__ __forceinline__ u64 fma2(u64 a, u64 b, u64 c) {
    u64 d; asm("fma.rn.f32x2 %0,%1,%2,%3;" : "=l"(d) : "l"(a), "l"(b), "l"(c)); return d;
}
__device__ __forceinline__ u64 mul2(u64 a, u64 b) {
    u64 d; asm("mul.rn.f32x2 %0,%1,%2;" : "=l"(d) : "l"(a), "l"(b)); return d;
}
__device__ __forceinline__ u64 add2(u64 a, u64 b) {
    u64 d; asm("add.rn.f32x2 %0,%1,%2;" : "=l"(d) : "l"(a), "l"(b)); return d;
}

__global__ __launch_bounds__(THREADS)
void attn_fused_kernel(
    const float* __restrict__ x,     const float* __restrict__ mask,
    const float* __restrict__ Wq,    const float* __restrict__ bq,
    const float* __restrict__ Wk,    const float* __restrict__ bk,
    const float* __restrict__ Wv,    const float* __restrict__ bv,
    const float* __restrict__ gamma, const float* __restrict__ beta,
    float* __restrict__ out, int B)
{
    __shared__ alignas(16) u64 sW[3][4][KVD][6];
    __shared__ alignas(16) u64 sB[3][4][6];
    __shared__ alignas(16) u64 sG[6], sBt[6];
    __shared__ float sMaskF[32];
    __shared__ alignas(16) u64 sKV[WPB][SPW][NQ][KVSTRIDE];
    __shared__ alignas(16) u64 sQ[WPB][SPW][NQ][QSTRIDE];
    __shared__ float sX[WPB][SPW][ROW];

    const int tid  = threadIdx.x;
    const int warp = tid >> 5;
    const int lane = tid & 31;

    // ---- repack constants (Wq,bq pre-scaled by 1/3; q aug slot = 1, k aug = mask*-1e9) ----
    for (int i = tid; i < 540; i += THREADS) {
        const int p  = i % 5;
        const int d  = (i / 5) % KVD;
        const int g  = (i / 45) % 4;
        const int pr = i / 180;
        const float* W = (pr == 0) ? Wq : (pr == 1) ? Wk : Wv;
        const float sc = (pr == 0) ? (1.0f / 3.0f) : 1.0f;
        const int e = 2 * p;
        const float lo = W[g * 81 + e * KVD + d] * sc;
        const float hi = (e + 1 < KVD) ? W[g * 81 + (e + 1) * KVD + d] * sc : 0.f;
        sW[pr][g][d][p] = pk(lo, hi);
    }
    for (int i = tid; i < 60; i += THREADS) {
        const int p  = i % 5;
        const int g  = (i / 5) % 4;
        const int pr = i / 20;
        const float* Bb = (pr == 0) ? bq : (pr == 1) ? bk : bv;
        const float sc = (pr == 0) ? (1.0f / 3.0f) : 1.0f;
        const int e = 2 * p;
        const float lo = Bb[g * KVD + e] * sc;
        float hi;
        if (e + 1 < KVD) hi = Bb[g * KVD + e + 1] * sc;
        else             hi = (pr == 0) ? 1.0f : 0.0f;
        sB[pr][g][p] = pk(lo, hi);
    }
    if (tid < 5) {
        const int e = 2 * tid;
        sG[tid]  = pk(gamma[e], (e + 1 < KVD) ? gamma[e + 1] : 0.f);
        sBt[tid] = pk(beta[e],  (e + 1 < KVD) ? beta[e + 1]  : 0.f);
    }
    if (tid < NQ) sMaskF[tid] = mask[tid] * -1e9f;
    __syncthreads();

    const long s0 = (long)blockIdx.x * SPB + warp * SPW;
    long nrem = (long)B - s0;
    const int cnt = (nrem <= 0) ? 0 : (nrem >= SPW ? SPW : (int)nrem);

    // ---- coalesced input staging (up to 4 samples contiguous) ----
    float* sxAll = &sX[warp][0][0];
    {
        const float* xrow = x + s0 * ROW;
        for (int i = lane; i < cnt * ROW; i += 32) sxAll[i] = xrow[i];
    }
    __syncwarp();

    // ---- phase 1: two passes, 2 samples each; item = lane ----
    #pragma unroll
    for (int pass = 0; pass < 2; pass++) {
        const int selA = 2 * pass, selB = 2 * pass + 1;
        if (lane < NQ) {
            const int g = (lane < 3) ? 0 : (lane < 13) ? 1 : (lane < 23) ? 2 : 3;
            float xa[KVD], xb[KVD];
            #pragma unroll
            for (int d = 0; d < KVD; d++) {
                xa[d] = sX[warp][selA][lane * KVD + d];
                xb[d] = sX[warp][selB][lane * KVD + d];
            }
            const float mterm = sMaskF[lane];
            u64* ra = &sKV[warp][selA][lane][0];
            u64* rb = &sKV[warp][selB][lane][0];

            // --- K ---
            {
                u64 kA[5], kB[5];
                #pragma unroll
                for (int p = 0; p < 5; p++) { kA[p] = sB[1][g][p]; kB[p] = kA[p]; }
                #pragma unroll
                for (int d = 0; d < KVD; d++) {
                    const u64 x0 = pk(xa[d], xa[d]);
                    const u64 x1 = pk(xb[d], xb[d]);
                    const u64* w = &sW[1][g][d][0];
                    const ulonglong2 w01 = *(const ulonglong2*)w;
                    const ulonglong2 w23 = *(const ulonglong2*)(w + 2);
                    const u64 w4 = w[4];
                    kA[0]=fma2(x0,w01.x,kA[0]); kA[1]=fma2(x0,w01.y,kA[1]);
                    kA[2]=fma2(x0,w23.x,kA[2]); kA[3]=fma2(x0,w23.y,kA[3]);
                    kA[4]=fma2(x0,w4,   kA[4]);
                    kB[0]=fma2(x1,w01.x,kB[0]); kB[1]=fma2(x1,w01.y,kB[1]);
                    kB[2]=fma2(x1,w23.x,kB[2]); kB[3]=fma2(x1,w23.y,kB[3]);
                    kB[4]=fma2(x1,w4,   kB[4]);
                }
                float klo, khi;
                unpk(kA[4], klo, khi);
                *(ulonglong2*)(ra + 0) = make_ulonglong2(kA[0], kA[1]);
                *(ulonglong2*)(ra + 2) = make_ulonglong2(kA[2], kA[3]);
                ra[4] = pk(klo, mterm);
                unpk(kB[4], klo, khi);
                *(ulonglong2*)(rb + 0) = make_ulonglong2(kB[0], kB[1]);
                *(ulonglong2*)(rb + 2) = make_ulonglong2(kB[2], kB[3]);
                rb[4] = pk(klo, mterm);
            }
            // --- V ---
            {
                u64 vA[5], vB[5];
                #pragma unroll
                for (int p = 0; p < 5; p++) { vA[p] = sB[2][g][p]; vB[p] = vA[p]; }
                #pragma unroll
                for (int d = 0; d < KVD; d++) {
                    const u64 x0 = pk(xa[d], xa[d]);
                    const u64 x1 = pk(xb[d], xb[d]);
                    const u64* w = &sW[2][g][d][0];
                    const ulonglong2 w01 = *(const ulonglong2*)w;
                    const ulonglong2 w23 = *(const ulonglong2*)(w + 2);
                    const u64 w4 = w[4];
                    vA[0]=fma2(x0,w01.x,vA[0]); vA[1]=fma2(x0,w01.y,vA[1]);
                    vA[2]=fma2(x0,w23.x,vA[2]); vA[3]=fma2(x0,w23.y,vA[3]);
                    vA[4]=fma2(x0,w4,   vA[4]);
                    vB[0]=fma2(x1,w01.x,vB[0]); vB[1]=fma2(x1,w01.y,vB[1]);
                    vB[2]=fma2(x1,w23.x,vB[2]); vB[3]=fma2(x1,w23.y,vB[3]);
                    vB[4]=fma2(x1,w4,   vB[4]);
                }
                *(ulonglong2*)(ra + 6) = make_ulonglong2(vA[0], vA[1]);
                *(ulonglong2*)(ra + 8) = make_ulonglong2(vA[2], vA[3]);
                ra[10] = vA[4];
                *(ulonglong2*)(rb + 6) = make_ulonglong2(vB[0], vB[1]);
                *(ulonglong2*)(rb + 8) = make_ulonglong2(vB[2], vB[3]);
                rb[10] = vB[4];
            }
            // --- Q ---
            {
                u64 qA[5], qB[5];
                #pragma unroll
                for (int p = 0; p < 5; p++) { qA[p] = sB[0][g][p]; qB[p] = qA[p]; }
                #pragma unroll
                for (int d = 0; d < KVD; d++) {
                    const u64 x0 = pk(xa[d], xa[d]);
                    const u64 x1 = pk(xb[d], xb[d]);
                    const u64* w = &sW[0][g][d][0];
                    const ulonglong2 w01 = *(const ulonglong2*)w;
                    const ulonglong2 w23 = *(const ulonglong2*)(w + 2);
                    const u64 w4 = w[4];
                    qA[0]=fma2(x0,w01.x,qA[0]); qA[1]=fma2(x0,w01.y,qA[1]);
                    qA[2]=fma2(x0,w23.x,qA[2]); qA[3]=fma2(x0,w23.y,qA[3]);
                    qA[4]=fma2(x0,w4,   qA[4]);
                    qB[0]=fma2(x1,w01.x,qB[0]); qB[1]=fma2(x1,w01.y,qB[1]);
                    qB[2]=fma2(x1,w23.x,qB[2]); qB[3]=fma2(x1,w23.y,qB[3]);
                    qB[4]=fma2(x1,w4,   qB[4]);
                }
                #pragma unroll
                for (int p = 0; p < 5; p++) {
                    sQ[warp][selA][lane][p] = qA[p];
                    sQ[warp][selB][lane][p] = qB[p];
                }
            }
        }
    }
    __syncwarp();

    // ---- phase 2: 28 lanes = 4 samples x 7 lanes; 4 q-rows per lane ----
    if (lane < 28) {
        const int sel = lane / 7;        // sample within warp
        const int idx = lane % 7;        // row-block 0..6
        const int base_row = 4 * idx;    // rows base_row..base_row+3 (clamped)

        u64 q[4][5];
        #pragma unroll
        for (int s = 0; s < 4; s++) {
            const int row = (base_row + s < NQ) ? base_row + s : NQ - 1;
            #pragma unroll
            for (int p = 0; p < 5; p++) q[s][p] = sQ[warp][sel][row][p];
        }

        u64 o[4][5];
        float sum[4] = {0.f, 0.f, 0.f, 0.f};
        #pragma unroll
        for (int s = 0; s < 4; s++)
            #pragma unroll
            for (int p = 0; p < 5; p++) o[s][p] = 0;

        const u64* base = &sKV[warp][sel][0][0];
        #pragma unroll
        for (int j = 0; j < NQ; j++) {
            const u64* r = base + j * KVSTRIDE;
            const ulonglong2 k01 = *(const ulonglong2*)r;
            const ulonglong2 k23 = *(const ulonglong2*)(r + 2);
            const u64 k4 = r[4];
            u64 ep[4];
            #pragma unroll
            for (int s = 0; s < 4; s++) {
                u64 acc = mul2(q[s][0], k01.x);
                acc = fma2(q[s][1], k01.y, acc);
                acc = fma2(q[s][2], k23.x, acc);
                acc = fma2(q[s][3], k23.y, acc);
                acc = fma2(q[s][4], k4,    acc);
                float lo, hi; unpk(acc, lo, hi);
                const float e = __expf(lo + hi);
                sum[s] += e;
                ep[s] = pk(e, e);
            }
            const ulonglong2 v01 = *(const ulonglong2*)(r + 6);
            const ulonglong2 v23 = *(const ulonglong2*)(r + 8);
            const u64 v4 = r[10];
            #pragma unroll
            for (int s = 0; s < 4; s++) {
                o[s][0] = fma2(ep[s], v01.x, o[s][0]);
                o[s][1] = fma2(ep[s], v01.y, o[s][1]);
                o[s][2] = fma2(ep[s], v23.x, o[s][2]);
                o[s][3] = fma2(ep[s], v23.y, o[s][3]);
                o[s][4] = fma2(ep[s], v4,    o[s][4]);
            }
        }

        // ---- epilogue per q-row (skip clamped duplicates) ----
        float g8, b8, zz;
        unpk(sG[4], g8, zz); unpk(sBt[4], b8, zz);
        #pragma unroll
        for (int s = 0; s < 4; s++) {
            if (s > 0 && base_row + s >= NQ) break;
            const int row = base_row + s;
            float xr[KVD];
            #pragma unroll
            for (int d = 0; d < KVD; d++) xr[d] = sX[warp][sel][row * KVD + d];

            const float inv = 1.0f / sum[s];
            const u64 inv2 = pk(inv, inv);
            const u64 f0 = fma2(o[s][0], inv2, pk(xr[0], xr[1]));
            const u64 f1 = fma2(o[s][1], inv2, pk(xr[2], xr[3]));
            const u64 f2 = fma2(o[s][2], inv2, pk(xr[4], xr[5]));
            const u64 f3 = fma2(o[s][3], inv2, pk(xr[6], xr[7]));
            const u64 f4 = fma2(o[s][4], inv2, pk(xr[8], 0.f));

            float e0,e1,e2,e3,e4,e5,e6,e7,e8,ez;
            unpk(f0, e0, e1); unpk(f1, e2, e3);
            unpk(f2, e4, e5); unpk(f3, e6, e7);
            unpk(f4, e8, ez);
            const float mu = (e0+e1+e2+e3+e4+e5+e6+e7+e8) * (1.0f/9.0f);
            const u64 nmu2 = pk(-mu, -mu);
            const u64 t0 = add2(f0, nmu2);
            const u64 t1 = add2(f1, nmu2);
            const u64 t2 = add2(f2, nmu2);
            const u64 t3 = add2(f3, nmu2);
            const float t8 = e8 - mu;
            u64 vacc = mul2(t0, t0);
            vacc = fma2(t1, t1, vacc);
            vacc = fma2(t2, t2, vacc);
            vacc = fma2(t3, t3, vacc);
            float va0, va1; unpk(vacc, va0, va1);
            const float var = (va0 + va1 + t8 * t8) * (1.0f/9.0f);
            const float rinv = rsqrtf(var + 1e-5f);
            const u64 rinv2 = pk(rinv, rinv);

            const u64 r0p = fma2(mul2(t0, rinv2), sG[0], sBt[0]);
            const u64 r1p = fma2(mul2(t1, rinv2), sG[1], sBt[1]);
            const u64 r2p = fma2(mul2(t2, rinv2), sG[2], sBt[2]);
            const u64 r3p = fma2(mul2(t3, rinv2), sG[3], sBt[3]);
            const float r8 = t8 * rinv * g8 + b8;

            float w0,w1,w2,w3,w4,w5,w6,w7;
            unpk(r0p,w0,w1); unpk(r1p,w2,w3); unpk(r2p,w4,w5); unpk(r3p,w6,w7);
            float* so = &sX[warp][sel][row * KVD];
            so[0]=w0; so[1]=w1; so[2]=w2; so[3]=w3;
            so[4]=w4; so[5]=w5; so[6]=w6; so[7]=w7; so[8]=r8;
        }
    }
    __syncwarp();

    // ---- coalesced output ----
    {
        float* orow = out + s0 * ROW;
        for (int i = lane; i < cnt * ROW; i += 32) orow[i] = sxAll[i];
    }
}

extern "C" void kernel_launch(void* const* d_in, const int* in_sizes, int n_in,
                              void* d_out, int out_size)
{
    const float* x     = (const float*)d_in[0];
    const float* mask  = (const float*)d_in[1];
    const float* Wq    = (const float*)d_in[2];
    const float* bq    = (const float*)d_in[3];
    const float* Wk    = (const float*)d_in[4];
    const float* bk    = (const float*)d_in[5];
    const float* Wv    = (const float*)d_in[6];
    const float* bv    = (const float*)d_in[7];
    const float* gamma = (const float*)d_in[8];
    const float* beta  = (const float*)d_in[9];
    float* out = (float*)d_out;

    const int B = in_sizes[0] / ROW;
    const int blocks = (B + SPB - 1) / SPB;
    attn_fused_kernel<<<blocks, THREADS>>>(x, mask, Wq, bq, Wk, bk, Wv, bv,
                                           gamma, beta, out, B);
}